// round 13
// baseline (speedup 1.0000x reference)
#include <cuda_runtime.h>
#include <cuda_bf16.h>
#include <stdint.h>

// ScaledDotProductAttention (reference semantics, unstable exp):
//   s = (q·k)/8 ; s[mask]=0 ; e=exp(s) ; attn=e/rowsum(e) ; out=attn·v
// Split-bf16 mma.sync. A pre-pass kernel splits Q (prescaled by 0.125*log2e),
// K, V into bf16 hi/lo planes in __device__ scratch once; the main kernel
// cp.asyncs those planes directly into double-buffered SMEM (no per-tile
// conversion). 16 warps (8 q x 2 k).

#define LQ 2048
#define LK 2048
#define DH 64
#define BQ 128
#define BK 128
#define NTILES (LK / BK)
#define NTHREADS 512
#define BMAX 16

#define QK_SCALE 0.18033688011112042f   // 0.125 * log2(e)

#define TSTRIDE 144                    // bf16 tile row stride (bytes)
#define TILE_BYTES (128 * TSTRIDE)     // 18432
// SMEM layout
#define SM_QH   0
#define SM_QL   (SM_QH + TILE_BYTES)
#define SM_KV0  (SM_QL + TILE_BYTES)          // stage0: KH,KL,VH,VL
#define KV_STAGE_BYTES (4 * TILE_BYTES)       // 73728
#define SM_KV1  (SM_KV0 + KV_STAGE_BYTES)
#define OFF_KH  0
#define OFF_KL  TILE_BYTES
#define OFF_VH  (2 * TILE_BYTES)
#define OFF_VL  (3 * TILE_BYTES)
#define MSTRIDE 136
#define SM_MS   (SM_KV1 + KV_STAGE_BYTES)     // mask 128x136 = 17408
#define SM_DEN  (SM_MS + 128 * MSTRIDE)       // den partials 1024B
#define SM_TOTAL (SM_DEN + 1024)              // 202752
#define SM_OSM  SM_KV0                        // O partial buffer (dead stage0)
#define OSTRIDE 288

// =================== device scratch: split planes ===================
#define NELEM (BMAX * LQ * DH)                 // 2M elements per plane
__device__ __align__(128) __nv_bfloat16 g_qh[NELEM];
__device__ __align__(128) __nv_bfloat16 g_ql[NELEM];
__device__ __align__(128) __nv_bfloat16 g_kh[NELEM];
__device__ __align__(128) __nv_bfloat16 g_kl[NELEM];
__device__ __align__(128) __nv_bfloat16 g_vh[NELEM];
__device__ __align__(128) __nv_bfloat16 g_vl[NELEM];

// =================== helpers ===================
__device__ __forceinline__ uint32_t smem_u32(const void* p) {
    uint32_t a;
    asm("{ .reg .u64 t; cvta.to.shared.u64 t, %1; cvt.u32.u64 %0, t; }" : "=r"(a) : "l"(p));
    return a;
}
__device__ __forceinline__ void ldsm_x4(uint32_t* r, uint32_t a) {
    asm volatile("ldmatrix.sync.aligned.m8n8.x4.shared.b16 {%0,%1,%2,%3}, [%4];"
                 : "=r"(r[0]), "=r"(r[1]), "=r"(r[2]), "=r"(r[3]) : "r"(a));
}
__device__ __forceinline__ void ldsm_x4_t(uint32_t* r, uint32_t a) {
    asm volatile("ldmatrix.sync.aligned.m8n8.x4.trans.shared.b16 {%0,%1,%2,%3}, [%4];"
                 : "=r"(r[0]), "=r"(r[1]), "=r"(r[2]), "=r"(r[3]) : "r"(a));
}
__device__ __forceinline__ void mma16816(float* c, const uint32_t* a, const uint32_t* b) {
    asm volatile("mma.sync.aligned.m16n8k16.row.col.f32.bf16.bf16.f32 "
                 "{%0,%1,%2,%3}, {%4,%5,%6,%7}, {%8,%9}, {%0,%1,%2,%3};"
                 : "+f"(c[0]), "+f"(c[1]), "+f"(c[2]), "+f"(c[3])
                 : "r"(a[0]), "r"(a[1]), "r"(a[2]), "r"(a[3]), "r"(b[0]), "r"(b[1]));
}
__device__ __forceinline__ float ex2f(float x) {
    float r;
    asm("ex2.approx.f32 %0, %1;" : "=f"(r) : "f"(x));
    return r;
}
__device__ __forceinline__ void split_pair(uint32_t& hp, uint32_t& lp, float a, float b) {
    asm("cvt.rn.bf16x2.f32 %0, %1, %2;" : "=r"(hp) : "f"(b), "f"(a));   // lo16=a, hi16=b
    float ha = __uint_as_float(hp << 16);
    float hb = __uint_as_float(hp & 0xFFFF0000u);
    float ra = a - ha, rb = b - hb;
    asm("cvt.rn.bf16x2.f32 %0, %1, %2;" : "=r"(lp) : "f"(rb), "f"(ra));
}

#define CP_ASYNC16(sm, gp) \
    asm volatile("cp.async.cg.shared.global [%0], [%1], 16;" :: "r"(sm), "l"(gp) : "memory")
#define CP_COMMIT() asm volatile("cp.async.commit_group;" ::: "memory")
#define CP_WAIT0()  asm volatile("cp.async.wait_group 0;" ::: "memory")
#define CP_WAIT1()  asm volatile("cp.async.wait_group 1;" ::: "memory")

// cp.async one 128x64 bf16 plane (128 B rows) into SMEM at TSTRIDE rows
__device__ __forceinline__ void cp_plane(const __nv_bfloat16* __restrict__ src,
                                         size_t elem_base, uint32_t dst, int tid) {
    const int row = tid >> 2, q = tid & 3;
    const char* gp = (const char*)(src + elem_base + (size_t)row * DH) + q * 32;
    const uint32_t d = dst + row * TSTRIDE + q * 32;
    CP_ASYNC16(d, gp);
    CP_ASYNC16(d + 16, gp + 16);
}

// =================== pre-pass: fp32 -> split bf16 hi/lo planes ===================
__global__ void split_prepass(const float* __restrict__ Q, const float* __restrict__ K,
                              const float* __restrict__ V) {
    const int which = blockIdx.y;
    const float* src = (which == 0) ? Q : (which == 1) ? K : V;
    uint32_t* dh = (uint32_t*)((which == 0) ? g_qh : (which == 1) ? g_kh : g_vh);
    uint32_t* dl = (uint32_t*)((which == 0) ? g_ql : (which == 1) ? g_kl : g_vl);
    const float sc = (which == 0) ? QK_SCALE : 1.0f;
    const size_t i = ((size_t)blockIdx.x * blockDim.x + threadIdx.x) * 4;
    float4 f = *(const float4*)(src + i);
    f.x *= sc; f.y *= sc; f.z *= sc; f.w *= sc;
    uint32_t h0, l0, h1, l1;
    split_pair(h0, l0, f.x, f.y);
    split_pair(h1, l1, f.z, f.w);
    dh[i / 2] = h0; dh[i / 2 + 1] = h1;
    dl[i / 2] = l0; dl[i / 2 + 1] = l1;
}

// =================== mask encoding detection (parallel) ===================
__device__ int g_mask_words;   // 0 = u8 bytes, 1 = 4-byte words

__global__ void detect_mask_kernel(const unsigned int* __restrict__ m) {
    __shared__ int bad;
    if (threadIdx.x == 0) bad = 0;
    __syncthreads();
    int ok = 1;
    for (int i = threadIdx.x; i < 4096; i += 256) {
        unsigned int w = m[i];
        if (w != 0u && w != 1u && w != 0x3F800000u) ok = 0;
    }
    if (!ok) bad = 1;
    __syncthreads();
    if (threadIdx.x == 0) g_mask_words = bad ? 0 : 1;
}

// =================== main kernel ===================
__global__ void __launch_bounds__(NTHREADS, 1)
attn_mma_kernel(const void* __restrict__ Mraw, float* __restrict__ O) {
    extern __shared__ char sm[];
    const uint32_t smb = smem_u32(sm);
    const int tid  = threadIdx.x;
    const int w    = tid >> 5;
    const int lane = tid & 31;
    const int wq   = w & 7;             // q block: rows wq*16 .. +15
    const int wk   = w >> 3;            // k half:  keys wk*64 .. +63
    const int g    = lane >> 2;
    const int t4   = lane & 3;

    const int b  = blockIdx.y;
    const int q0 = blockIdx.x * BQ;
    const int mask_words = g_mask_words;

    const size_t qbase  = ((size_t)b * LQ + q0) * DH;
    const size_t kvb    = (size_t)b * LK * DH;
    const size_t mbase  = ((size_t)b * LQ + q0) * (size_t)LK;

    // ldmatrix lane geometry (add plane base at use)
    const uint32_t a_base  = smb + (uint32_t)(wq * 16 + (lane & 15)) * TSTRIDE + (lane >> 4) * 16;
    const uint32_t b4_geo  = smb + (uint32_t)(wk * 64 + (lane & 7) + ((lane & 16) >> 1)) * TSTRIDE
                           + ((lane >> 3) & 1) * 16;
    const uint32_t v4_geo  = smb + (uint32_t)(wk * 64 + (lane & 15)) * TSTRIDE + (lane >> 4) * 16;
    const char* m_row = sm + SM_MS + (wq * 16 + g) * MSTRIDE + wk * 64 + 2 * t4;

    // ---- prologue: G0 = Q planes + KV tile0 into stage0 ----
    cp_plane(g_qh, qbase, smb + SM_QH, tid);
    cp_plane(g_ql, qbase, smb + SM_QL, tid);
    cp_plane(g_kh, kvb, smb + SM_KV0 + OFF_KH, tid);
    cp_plane(g_kl, kvb, smb + SM_KV0 + OFF_KL, tid);
    cp_plane(g_vh, kvb, smb + SM_KV0 + OFF_VH, tid);
    cp_plane(g_vl, kvb, smb + SM_KV0 + OFF_VL, tid);
    CP_COMMIT();

    float oacc[8][4];
    #pragma unroll
    for (int j = 0; j < 8; j++)
        #pragma unroll
        for (int i = 0; i < 4; i++) oacc[j][i] = 0.0f;
    float den[2] = {0.0f, 0.0f};

    for (int t = 0; t < NTILES; t++) {
        __syncthreads();   // compute(t-1) done: mask smem + alternate KV stage free

        // ---- mask tile -> canonical u8 in SMEM ----
        {
            const int qrow = tid >> 2;
            const int mc0  = (tid & 3) << 5;       // 32-byte chunk
            char* dst = sm + SM_MS + qrow * MSTRIDE + mc0;
            const size_t e = mbase + (size_t)qrow * LK + (size_t)t * BK + mc0;
            if (mask_words) {
                const uint4* src = (const uint4*)((const unsigned int*)Mraw + e);
                #pragma unroll
                for (int i = 0; i < 8; i++) {
                    uint4 mw = src[i];
                    uint32_t p = (mw.x ? 1u : 0u) | (mw.y ? 0x100u : 0u)
                               | (mw.z ? 0x10000u : 0u) | (mw.w ? 0x1000000u : 0u);
                    *(uint32_t*)(dst + 4 * i) = p;
                }
            } else {
                const uint32_t* src = (const uint32_t*)((const unsigned char*)Mraw + e);
                #pragma unroll
                for (int i = 0; i < 8; i++) *(uint32_t*)(dst + 4 * i) = src[i];
            }
        }

        // ---- prefetch KV(t+1) into alternate stage ----
        if (t + 1 < NTILES) {
            const uint32_t nb = smb + ((t + 1) & 1 ? SM_KV1 : SM_KV0);
            const size_t e = kvb + (size_t)(t + 1) * BK * DH;
            cp_plane(g_kh, e, nb + OFF_KH, tid);
            cp_plane(g_kl, e, nb + OFF_KL, tid);
            cp_plane(g_vh, e, nb + OFF_VH, tid);
            cp_plane(g_vl, e, nb + OFF_VL, tid);
            CP_COMMIT();
            CP_WAIT1();    // group for tile t complete (t+1 still in flight)
        } else {
            CP_WAIT0();
        }
        __syncthreads();   // KV(t) + mask visible to all

        const uint32_t kvbase = (t & 1 ? SM_KV1 : SM_KV0);

        // ---- S = Qh·Kh + Ql·Kh + Qh·Kl  (16 rows x 64 keys per warp) ----
        float sacc[8][4];
        #pragma unroll
        for (int nt = 0; nt < 8; nt++)
            #pragma unroll
            for (int i = 0; i < 4; i++) sacc[nt][i] = 0.0f;

        const uint32_t kh_b = b4_geo + kvbase + OFF_KH;
        const uint32_t kl_b = b4_geo + kvbase + OFF_KL;
        #pragma unroll
        for (int kt = 0; kt < 4; kt++) {
            uint32_t ah[4], al[4];
            ldsm_x4(ah, a_base + SM_QH + kt * 32);
            ldsm_x4(al, a_base + SM_QL + kt * 32);
            #pragma unroll
            for (int nt2 = 0; nt2 < 4; nt2++) {
                uint32_t bh4[4], bl4[4];
                ldsm_x4(bh4, kh_b + nt2 * (16 * TSTRIDE) + kt * 32);
                ldsm_x4(bl4, kl_b + nt2 * (16 * TSTRIDE) + kt * 32);
                mma16816(sacc[2 * nt2],     ah, bh4);
                mma16816(sacc[2 * nt2],     al, bh4);
                mma16816(sacc[2 * nt2],     ah, bl4);
                mma16816(sacc[2 * nt2 + 1], ah, bh4 + 2);
                mma16816(sacc[2 * nt2 + 1], al, bh4 + 2);
                mma16816(sacc[2 * nt2 + 1], ah, bl4 + 2);
            }
        }

        // ---- epilogue + PV per 16-key group ----
        const uint32_t vh_b = v4_geo + kvbase + OFF_VH;
        const uint32_t vl_b = v4_geo + kvbase + OFF_VL;
        #pragma unroll
        for (int kt2 = 0; kt2 < 4; kt2++) {
            uint32_t vfh[16], vfl[16];
            #pragma unroll
            for (int jj = 0; jj < 4; jj++) {
                ldsm_x4_t(vfh + 4 * jj, vh_b + kt2 * (16 * TSTRIDE) + jj * 32);
                ldsm_x4_t(vfl + 4 * jj, vl_b + kt2 * (16 * TSTRIDE) + jj * 32);
            }
            const int n0 = 2 * kt2, n1 = n0 + 1;
            const char* mr1 = m_row + 8 * MSTRIDE;
            uint16_t mA0 = *(const uint16_t*)(m_row + n0 * 8);
            uint16_t mB0 = *(const uint16_t*)(mr1 + n0 * 8);
            uint16_t mA1 = *(const uint16_t*)(m_row + n1 * 8);
            uint16_t mB1 = *(const uint16_t*)(mr1 + n1 * 8);

            float p00 = ex2f((mA0 & 0xFF) ? 0.0f : sacc[n0][0]);
            float p01 = ex2f((mA0 >> 8)   ? 0.0f : sacc[n0][1]);
            float p02 = ex2f((mB0 & 0xFF) ? 0.0f : sacc[n0][2]);
            float p03 = ex2f((mB0 >> 8)   ? 0.0f : sacc[n0][3]);
            float p10 = ex2f((mA1 & 0xFF) ? 0.0f : sacc[n1][0]);
            float p11 = ex2f((mA1 >> 8)   ? 0.0f : sacc[n1][1]);
            float p12 = ex2f((mB1 & 0xFF) ? 0.0f : sacc[n1][2]);
            float p13 = ex2f((mB1 >> 8)   ? 0.0f : sacc[n1][3]);

            den[0] += p00 + p01 + p10 + p11;
            den[1] += p02 + p03 + p12 + p13;

            uint32_t ph[4], pl[4];
            split_pair(ph[0], pl[0], p00, p01);
            split_pair(ph[1], pl[1], p02, p03);
            split_pair(ph[2], pl[2], p10, p11);
            split_pair(ph[3], pl[3], p12, p13);

            #pragma unroll
            for (int jj = 0; jj < 4; jj++) {
                mma16816(oacc[2 * jj],     ph, vfh + 4 * jj);
                mma16816(oacc[2 * jj],     pl, vfh + 4 * jj);
                mma16816(oacc[2 * jj],     ph, vfl + 4 * jj);
                mma16816(oacc[2 * jj + 1], ph, vfh + 4 * jj + 2);
                mma16816(oacc[2 * jj + 1], pl, vfh + 4 * jj + 2);
                mma16816(oacc[2 * jj + 1], ph, vfl + 4 * jj + 2);
            }
        }
    }

    // ---- quad-reduce den, publish partials ----
    #pragma unroll
    for (int h = 0; h < 2; h++) {
        den[h] += __shfl_xor_sync(0xFFFFFFFFu, den[h], 1);
        den[h] += __shfl_xor_sync(0xFFFFFFFFu, den[h], 2);
    }
    float* den_s = (float*)(sm + SM_DEN);
    if (t4 == 0) {
        den_s[wk * 128 + wq * 16 + g]     = den[0];
        den_s[wk * 128 + wq * 16 + g + 8] = den[1];
    }
    __syncthreads();   // all PV reads done; den partials visible

    // ---- wk=1 warps publish O partials into dead stage-0 SMEM ----
    if (wk == 1) {
        const int r0 = wq * 16 + g;
        char* base0 = sm + SM_OSM + r0 * OSTRIDE + 8 * t4;
        char* base1 = base0 + 8 * OSTRIDE;
        #pragma unroll
        for (int j = 0; j < 8; j++) {
            *(float2*)(base0 + j * 32) = make_float2(oacc[j][0], oacc[j][1]);
            *(float2*)(base1 + j * 32) = make_float2(oacc[j][2], oacc[j][3]);
        }
    }
    __syncthreads();

    // ---- wk=0 warps combine + normalize + write ----
    if (wk == 0) {
        const int r0 = wq * 16 + g;
        const float inv0 = 1.0f / (den_s[r0] + den_s[128 + r0]);
        const float inv1 = 1.0f / (den_s[r0 + 8] + den_s[128 + r0 + 8]);
        const char* base0 = sm + SM_OSM + r0 * OSTRIDE + 8 * t4;
        const char* base1 = base0 + 8 * OSTRIDE;
        float* o0 = O + ((size_t)b * LQ + q0 + r0) * DH + 2 * t4;
        float* o1 = o0 + 8 * DH;
        #pragma unroll
        for (int j = 0; j < 8; j++) {
            float2 q0v = *(const float2*)(base0 + j * 32);
            float2 q1v = *(const float2*)(base1 + j * 32);
            *(float2*)(o0 + 8 * j) = make_float2((oacc[j][0] + q0v.x) * inv0,
                                                 (oacc[j][1] + q0v.y) * inv0);
            *(float2*)(o1 + 8 * j) = make_float2((oacc[j][2] + q1v.x) * inv1,
                                                 (oacc[j][3] + q1v.y) * inv1);
        }
    }
}

extern "C" void kernel_launch(void* const* d_in, const int* in_sizes, int n_in,
                              void* d_out, int out_size) {
    int mask_idx = 0;
    for (int i = 1; i < n_in; i++)
        if (in_sizes[i] > in_sizes[mask_idx]) mask_idx = i;

    const float* qkv[3];
    int nq = 0;
    for (int i = 0; i < n_in && nq < 3; i++)
        if (i != mask_idx) qkv[nq++] = (const float*)d_in[i];

    const float* q = qkv[0];
    const float* k = qkv[1];
    const float* v = qkv[2];
    const void*  m = d_in[mask_idx];
    float* o = (float*)d_out;

    const int B = in_sizes[mask_idx] / (LQ * LK);

    cudaFuncSetAttribute(attn_mma_kernel,
                         cudaFuncAttributeMaxDynamicSharedMemorySize, SM_TOTAL);

    detect_mask_kernel<<<1, 256>>>((const unsigned int*)m);

    // pre-pass: split Q/K/V into bf16 hi/lo planes (1024 elems per block)
    dim3 pgrid((unsigned)(((size_t)B * LQ * DH) / 1024), 3);
    split_prepass<<<pgrid, 256>>>(q, k, v);

    dim3 grid(LQ / BQ, B);
    attn_mma_kernel<<<grid, NTHREADS, SM_TOTAL>>>(m, o);
}

// round 14
// speedup vs baseline: 1.1402x; 1.1402x over previous
#include <cuda_runtime.h>
#include <cuda_fp16.h>
#include <stdint.h>

// ScaledDotProductAttention (reference semantics, unstable exp):
//   s = (q·k)/8 ; s[mask]=0 ; e=exp(s) ; attn=e/rowsum(e) ; out=attn·v
// Split-fp16 mma.sync, cp.async-staged K/V, exp2-prescaled Q.
//   S  = Qh·Kh + Ql·Kh + Qh·Kl      (fp16 split: residual ~2^-22)
//   O += Ph·Vh + Ph·Vl              (P single fp16: error ~2^-11 -> ~3e-4)
// 16 warps (8 q-warps x 2 k-warps).

#define LQ 2048
#define LK 2048
#define DH 64
#define BQ 128
#define BK 128
#define NTILES (LK / BK)
#define NTHREADS 512

#define QK_SCALE 0.18033688011112042f   // 0.125 * log2(e)

#define TSTRIDE 144                    // fp16 tile row stride (bytes)
#define TILE_BYTES (128 * TSTRIDE)     // 18432
#define SM_QH 0
#define SM_QL (SM_QH + TILE_BYTES)
#define SM_KH (SM_QL + TILE_BYTES)
#define SM_KL (SM_KH + TILE_BYTES)
#define SM_VH (SM_KL + TILE_BYTES)
#define SM_VL (SM_VH + TILE_BYTES)
#define MSTRIDE 136
#define SM_MS (SM_VL + TILE_BYTES)         // mask 128x136
#define SM_DEN (SM_MS + 128 * MSTRIDE)     // den partials 1024B
#define STSTRIDE 272                       // fp32 staging row stride
#define SM_STK (SM_DEN + 1024)
#define SM_STV (SM_STK + 128 * STSTRIDE)
#define SM_TOTAL (SM_STV + 128 * STSTRIDE) // 198656
#define SM_OSM SM_KH                       // O partial buffer (reuses K tiles)
#define OSTRIDE 288

// =================== helpers ===================
__device__ __forceinline__ uint32_t smem_u32(const void* p) {
    uint32_t a;
    asm("{ .reg .u64 t; cvta.to.shared.u64 t, %1; cvt.u32.u64 %0, t; }" : "=r"(a) : "l"(p));
    return a;
}
__device__ __forceinline__ void ldsm_x4(uint32_t* r, uint32_t a) {
    asm volatile("ldmatrix.sync.aligned.m8n8.x4.shared.b16 {%0,%1,%2,%3}, [%4];"
                 : "=r"(r[0]), "=r"(r[1]), "=r"(r[2]), "=r"(r[3]) : "r"(a));
}
__device__ __forceinline__ void ldsm_x4_t(uint32_t* r, uint32_t a) {
    asm volatile("ldmatrix.sync.aligned.m8n8.x4.trans.shared.b16 {%0,%1,%2,%3}, [%4];"
                 : "=r"(r[0]), "=r"(r[1]), "=r"(r[2]), "=r"(r[3]) : "r"(a));
}
__device__ __forceinline__ void mma16816(float* c, const uint32_t* a, const uint32_t* b) {
    asm volatile("mma.sync.aligned.m16n8k16.row.col.f32.f16.f16.f32 "
                 "{%0,%1,%2,%3}, {%4,%5,%6,%7}, {%8,%9}, {%0,%1,%2,%3};"
                 : "+f"(c[0]), "+f"(c[1]), "+f"(c[2]), "+f"(c[3])
                 : "r"(a[0]), "r"(a[1]), "r"(a[2]), "r"(a[3]), "r"(b[0]), "r"(b[1]));
}
__device__ __forceinline__ float ex2f(float x) {
    float r;
    asm("ex2.approx.f32 %0, %1;" : "=f"(r) : "f"(x));
    return r;
}
// fp32 pair -> fp16x2 hi + fp16x2 lo residual (lo16 = a, hi16 = b)
__device__ __forceinline__ void split_pair(uint32_t& hp, uint32_t& lp, float a, float b) {
    __half2 h = __floats2half2_rn(a, b);
    float2 hf = __half22float2(h);
    __half2 l = __floats2half2_rn(a - hf.x, b - hf.y);
    hp = *reinterpret_cast<uint32_t*>(&h);
    lp = *reinterpret_cast<uint32_t*>(&l);
}
__device__ __forceinline__ uint32_t pack_f16(float a, float b) {
    __half2 h = __floats2half2_rn(a, b);
    return *reinterpret_cast<uint32_t*>(&h);
}

#define CP_ASYNC16(sm, gp) \
    asm volatile("cp.async.cg.shared.global [%0], [%1], 16;" :: "r"(sm), "l"(gp) : "memory")
#define CP_COMMIT() asm volatile("cp.async.commit_group;" ::: "memory")
#define CP_WAIT0()  asm volatile("cp.async.wait_group 0;" ::: "memory")

// gmem fp32 tile (128x64) -> raw fp32 staging via cp.async (512 threads)
__device__ __forceinline__ void stage_tile(const float* __restrict__ g,
                                           uint32_t st_base, int tid) {
    const int row = tid >> 2, q = tid & 3;          // 64B chunk per thread
    const char* gp = (const char*)(g + (size_t)row * DH) + q * 64;
    const uint32_t sp = st_base + row * STSTRIDE + q * 64;
    #pragma unroll
    for (int u = 0; u < 4; u++) CP_ASYNC16(sp + u * 16, gp + u * 16);
}

// staging fp32 -> split fp16 hi/lo tiles (512 threads)
__device__ __forceinline__ void split_from_staging(const char* sm_ro, char* sm,
                                                   int st_off, int oh, int ol, int tid) {
    const int row = tid & 127, dq = tid >> 7;       // dq: 16-elem d-chunk 0..3
    const float4* sp = (const float4*)(sm_ro + st_off + row * STSTRIDE + dq * 64);
    char* hrow = sm + oh + row * TSTRIDE + dq * 32;
    char* lrow = sm + ol + row * TSTRIDE + dq * 32;
    #pragma unroll
    for (int u = 0; u < 4; u++) {
        float4 f = sp[u];
        uint32_t h0, l0, h1, l1;
        split_pair(h0, l0, f.x, f.y);
        split_pair(h1, l1, f.z, f.w);
        *(uint2*)(hrow + 8 * u) = make_uint2(h0, h1);
        *(uint2*)(lrow + 8 * u) = make_uint2(l0, l1);
    }
}

// Q: direct gmem load with prescale, split to hi/lo (512 threads)
__device__ __forceinline__ void load_q_split(const float* __restrict__ g, char* sm, int tid) {
    const int row = tid >> 2, d0 = (tid & 3) << 4;
    const float4* s4 = (const float4*)(g + (size_t)row * DH + d0);
    char* hrow = sm + SM_QH + row * TSTRIDE + d0 * 2;
    char* lrow = sm + SM_QL + row * TSTRIDE + d0 * 2;
    #pragma unroll
    for (int u = 0; u < 4; u++) {
        float4 f = s4[u];
        f.x *= QK_SCALE; f.y *= QK_SCALE; f.z *= QK_SCALE; f.w *= QK_SCALE;
        uint32_t h0, l0, h1, l1;
        split_pair(h0, l0, f.x, f.y);
        split_pair(h1, l1, f.z, f.w);
        *(uint2*)(hrow + 8 * u) = make_uint2(h0, h1);
        *(uint2*)(lrow + 8 * u) = make_uint2(l0, l1);
    }
}

// =================== mask encoding detection (parallel) ===================
__device__ int g_mask_words;   // 0 = u8 bytes, 1 = 4-byte words

__global__ void detect_mask_kernel(const unsigned int* __restrict__ m) {
    __shared__ int bad;
    if (threadIdx.x == 0) bad = 0;
    __syncthreads();
    int ok = 1;
    for (int i = threadIdx.x; i < 4096; i += 256) {
        unsigned int w = m[i];
        if (w != 0u && w != 1u && w != 0x3F800000u) ok = 0;
    }
    if (!ok) bad = 1;
    __syncthreads();
    if (threadIdx.x == 0) g_mask_words = bad ? 0 : 1;
}

// =================== main kernel ===================
__global__ void __launch_bounds__(NTHREADS, 1)
attn_mma_kernel(const float* __restrict__ Q, const float* __restrict__ K,
                const float* __restrict__ V, const void* __restrict__ Mraw,
                float* __restrict__ O) {
    extern __shared__ char sm[];
    const uint32_t smb = smem_u32(sm);
    const int tid  = threadIdx.x;
    const int w    = tid >> 5;
    const int lane = tid & 31;
    const int wq   = w & 7;             // q block: rows wq*16 .. +15
    const int wk   = w >> 3;            // k half:  keys wk*64 .. +63
    const int g    = lane >> 2;
    const int t4   = lane & 3;

    const int b  = blockIdx.y;
    const int q0 = blockIdx.x * BQ;
    const int mask_words = g_mask_words;

    const float* Qb = Q + ((size_t)b * LQ + q0) * DH;
    const float* Kb = K + (size_t)b * LK * DH;
    const float* Vb = V + (size_t)b * LK * DH;
    const size_t mbase = ((size_t)b * LQ + q0) * (size_t)LK;

    // ldmatrix lane bases
    const uint32_t a_base  = smb + (uint32_t)(wq * 16 + (lane & 15)) * TSTRIDE + (lane >> 4) * 16;
    const uint32_t b4_base = smb + (uint32_t)(wk * 64 + (lane & 7) + ((lane & 16) >> 1)) * TSTRIDE
                           + ((lane >> 3) & 1) * 16;
    const uint32_t v4_base = smb + (uint32_t)(wk * 64 + (lane & 15)) * TSTRIDE + (lane >> 4) * 16;
    const char* m_row = sm + SM_MS + (wq * 16 + g) * MSTRIDE + wk * 64 + 2 * t4;

    // ---- prologue: start staging tile 0, then Q split ----
    stage_tile(Kb, smb + SM_STK, tid);
    stage_tile(Vb, smb + SM_STV, tid);
    CP_COMMIT();

    load_q_split(Qb, sm, tid);

    float oacc[8][4];
    #pragma unroll
    for (int j = 0; j < 8; j++)
        #pragma unroll
        for (int i = 0; i < 4; i++) oacc[j][i] = 0.0f;
    float den[2] = {0.0f, 0.0f};

    for (int t = 0; t < NTILES; t++) {
        __syncthreads();   // previous tile's compute done

        // ---- mask tile -> canonical u8 in SMEM ----
        {
            const int qrow = tid >> 2;
            const int mc0  = (tid & 3) << 5;       // 32-byte chunk
            char* dst = sm + SM_MS + qrow * MSTRIDE + mc0;
            const size_t e = mbase + (size_t)qrow * LK + (size_t)t * BK + mc0;
            if (mask_words) {
                const uint4* src = (const uint4*)((const unsigned int*)Mraw + e);
                #pragma unroll
                for (int i = 0; i < 8; i++) {
                    uint4 mw = src[i];
                    uint32_t p = (mw.x ? 1u : 0u) | (mw.y ? 0x100u : 0u)
                               | (mw.z ? 0x10000u : 0u) | (mw.w ? 0x1000000u : 0u);
                    *(uint32_t*)(dst + 4 * i) = p;
                }
            } else {
                const uint32_t* src = (const uint32_t*)((const unsigned char*)Mraw + e);
                #pragma unroll
                for (int i = 0; i < 8; i++) *(uint32_t*)(dst + 4 * i) = src[i];
            }
        }

        // ---- staging(t) ready -> split to fp16 tiles ----
        CP_WAIT0();
        __syncthreads();
        split_from_staging(sm, sm, SM_STK, SM_KH, SM_KL, tid);
        split_from_staging(sm, sm, SM_STV, SM_VH, SM_VL, tid);
        __syncthreads();

        // ---- start staging t+1 (hidden under compute) ----
        if (t + 1 < NTILES) {
            stage_tile(Kb + (size_t)((t + 1) * BK) * DH, smb + SM_STK, tid);
            stage_tile(Vb + (size_t)((t + 1) * BK) * DH, smb + SM_STV, tid);
            CP_COMMIT();
        }

        // ---- S = Qh·Kh + Ql·Kh + Qh·Kl  (16 rows x 64 keys per warp) ----
        float sacc[8][4];
        #pragma unroll
        for (int nt = 0; nt < 8; nt++)
            #pragma unroll
            for (int i = 0; i < 4; i++) sacc[nt][i] = 0.0f;

        #pragma unroll
        for (int kt = 0; kt < 4; kt++) {
            uint32_t ah[4], al[4];
            ldsm_x4(ah, a_base + SM_QH + kt * 32);
            ldsm_x4(al, a_base + SM_QL + kt * 32);
            #pragma unroll
            for (int nt2 = 0; nt2 < 4; nt2++) {
                uint32_t bh4[4], bl4[4];
                ldsm_x4(bh4, b4_base + SM_KH + nt2 * (16 * TSTRIDE) + kt * 32);
                ldsm_x4(bl4, b4_base + SM_KL + nt2 * (16 * TSTRIDE) + kt * 32);
                mma16816(sacc[2 * nt2],     ah, bh4);
                mma16816(sacc[2 * nt2],     al, bh4);
                mma16816(sacc[2 * nt2],     ah, bl4);
                mma16816(sacc[2 * nt2 + 1], ah, bh4 + 2);
                mma16816(sacc[2 * nt2 + 1], al, bh4 + 2);
                mma16816(sacc[2 * nt2 + 1], ah, bl4 + 2);
            }
        }

        // ---- epilogue + PV per 16-key group (P single fp16; V split) ----
        #pragma unroll
        for (int kt2 = 0; kt2 < 4; kt2++) {
            const int n0 = 2 * kt2, n1 = n0 + 1;
            const char* mr1 = m_row + 8 * MSTRIDE;
            uint16_t mA0 = *(const uint16_t*)(m_row + n0 * 8);
            uint16_t mB0 = *(const uint16_t*)(mr1 + n0 * 8);
            uint16_t mA1 = *(const uint16_t*)(m_row + n1 * 8);
            uint16_t mB1 = *(const uint16_t*)(mr1 + n1 * 8);

            float p00 = ex2f((mA0 & 0xFF) ? 0.0f : sacc[n0][0]);
            float p01 = ex2f((mA0 >> 8)   ? 0.0f : sacc[n0][1]);
            float p02 = ex2f((mB0 & 0xFF) ? 0.0f : sacc[n0][2]);
            float p03 = ex2f((mB0 >> 8)   ? 0.0f : sacc[n0][3]);
            float p10 = ex2f((mA1 & 0xFF) ? 0.0f : sacc[n1][0]);
            float p11 = ex2f((mA1 >> 8)   ? 0.0f : sacc[n1][1]);
            float p12 = ex2f((mB1 & 0xFF) ? 0.0f : sacc[n1][2]);
            float p13 = ex2f((mB1 >> 8)   ? 0.0f : sacc[n1][3]);

            den[0] += p00 + p01 + p10 + p11;
            den[1] += p02 + p03 + p12 + p13;

            uint32_t ph[4];
            ph[0] = pack_f16(p00, p01);
            ph[1] = pack_f16(p02, p03);
            ph[2] = pack_f16(p10, p11);
            ph[3] = pack_f16(p12, p13);

            const uint32_t vrow = v4_base + kt2 * (16 * TSTRIDE);
            #pragma unroll
            for (int dh = 0; dh < 2; dh++) {      // d halves: 16-reg frag footprint
                uint32_t vfh[8], vfl[8];
                #pragma unroll
                for (int jj = 0; jj < 2; jj++) {
                    ldsm_x4_t(vfh + 4 * jj, vrow + SM_VH + (dh * 2 + jj) * 32);
                    ldsm_x4_t(vfl + 4 * jj, vrow + SM_VL + (dh * 2 + jj) * 32);
                }
                #pragma unroll
                for (int jj = 0; jj < 2; jj++) {
                    const int j = dh * 2 + jj;
                    mma16816(oacc[2 * j],     ph, vfh + 4 * jj);
                    mma16816(oacc[2 * j],     ph, vfl + 4 * jj);
                    mma16816(oacc[2 * j + 1], ph, vfh + 4 * jj + 2);
                    mma16816(oacc[2 * j + 1], ph, vfl + 4 * jj + 2);
                }
            }
        }
    }

    // ---- quad-reduce den, publish partials ----
    #pragma unroll
    for (int h = 0; h < 2; h++) {
        den[h] += __shfl_xor_sync(0xFFFFFFFFu, den[h], 1);
        den[h] += __shfl_xor_sync(0xFFFFFFFFu, den[h], 2);
    }
    float* den_s = (float*)(sm + SM_DEN);
    if (t4 == 0) {
        den_s[wk * 128 + wq * 16 + g]     = den[0];
        den_s[wk * 128 + wq * 16 + g + 8] = den[1];
    }
    __syncthreads();   // all PV reads of K/V SMEM done; den partials visible

    // ---- wk=1 warps publish O partials into reused K-tile SMEM ----
    if (wk == 1) {
        const int r0 = wq * 16 + g;
        char* base0 = sm + SM_OSM + r0 * OSTRIDE + 8 * t4;
        char* base1 = base0 + 8 * OSTRIDE;
        #pragma unroll
        for (int j = 0; j < 8; j++) {
            *(float2*)(base0 + j * 32) = make_float2(oacc[j][0], oacc[j][1]);
            *(float2*)(base1 + j * 32) = make_float2(oacc[j][2], oacc[j][3]);
        }
    }
    __syncthreads();

    // ---- wk=0 warps combine + normalize + write ----
    if (wk == 0) {
        const int r0 = wq * 16 + g;
        const float inv0 = 1.0f / (den_s[r0] + den_s[128 + r0]);
        const float inv1 = 1.0f / (den_s[r0 + 8] + den_s[128 + r0 + 8]);
        const char* base0 = sm + SM_OSM + r0 * OSTRIDE + 8 * t4;
        const char* base1 = base0 + 8 * OSTRIDE;
        float* o0 = O + ((size_t)b * LQ + q0 + r0) * DH + 2 * t4;
        float* o1 = o0 + 8 * DH;
        #pragma unroll
        for (int j = 0; j < 8; j++) {
            float2 q0v = *(const float2*)(base0 + j * 32);
            float2 q1v = *(const float2*)(base1 + j * 32);
            *(float2*)(o0 + 8 * j) = make_float2((oacc[j][0] + q0v.x) * inv0,
                                                 (oacc[j][1] + q0v.y) * inv0);
            *(float2*)(o1 + 8 * j) = make_float2((oacc[j][2] + q1v.x) * inv1,
                                                 (oacc[j][3] + q1v.y) * inv1);
        }
    }
}

extern "C" void kernel_launch(void* const* d_in, const int* in_sizes, int n_in,
                              void* d_out, int out_size) {
    int mask_idx = 0;
    for (int i = 1; i < n_in; i++)
        if (in_sizes[i] > in_sizes[mask_idx]) mask_idx = i;

    const float* qkv[3];
    int nq = 0;
    for (int i = 0; i < n_in && nq < 3; i++)
        if (i != mask_idx) qkv[nq++] = (const float*)d_in[i];

    const float* q = qkv[0];
    const float* k = qkv[1];
    const float* v = qkv[2];
    const void*  m = d_in[mask_idx];
    float* o = (float*)d_out;

    const int B = in_sizes[mask_idx] / (LQ * LK);

    cudaFuncSetAttribute(attn_mma_kernel,
                         cudaFuncAttributeMaxDynamicSharedMemorySize, SM_TOTAL);

    detect_mask_kernel<<<1, 256>>>((const unsigned int*)m);

    dim3 grid(LQ / BQ, B);
    attn_mma_kernel<<<grid, NTHREADS, SM_TOTAL>>>(q, k, v, m, o);
}

// round 15
// speedup vs baseline: 1.2213x; 1.0711x over previous
#include <cuda_runtime.h>
#include <cuda_fp16.h>
#include <stdint.h>

// ScaledDotProductAttention (reference semantics, unstable exp):
//   s = (q·k)/8 ; s[mask]=0 ; e=exp(s) ; attn=e/rowsum(e) ; out=attn·v
// fp16 mma.sync, cp.async-staged K/V, exp2-prescaled Q.
//   S  = Qh·Kh + Ql·Kh      (Q split fp16; K single fp16 -> s err ~2^-12)
//   O += Ph·Vh + Ph·Vl      (P single fp16; V split)
// Mask LDG issued before the split phase (latency hidden), STS after.
// 16 warps (8 q-warps x 2 k-warps).

#define LQ 2048
#define LK 2048
#define DH 64
#define BQ 128
#define BK 128
#define NTILES (LK / BK)
#define NTHREADS 512

#define QK_SCALE 0.18033688011112042f   // 0.125 * log2(e)

#define TSTRIDE 144                    // fp16 tile row stride (bytes)
#define TILE_BYTES (128 * TSTRIDE)     // 18432
#define SM_QH 0
#define SM_QL (SM_QH + TILE_BYTES)
#define SM_KH (SM_QL + TILE_BYTES)
#define SM_VH (SM_KH + TILE_BYTES)
#define SM_VL (SM_VH + TILE_BYTES)
#define MSTRIDE 136
#define SM_MS  (SM_VL + TILE_BYTES)        // 92160 mask 128x136
#define SM_DEN (SM_MS + 128 * MSTRIDE)     // 109568 den partials
#define STSTRIDE 272                       // fp32 staging row stride
#define SM_STK (SM_DEN + 1024)             // 110592
#define SM_STV (SM_STK + 128 * STSTRIDE)   // 145408
#define SM_TOTAL (SM_STV + 128 * STSTRIDE) // 180224
#define SM_OSM SM_QH                       // O partial buffer (dead Q tiles)
#define OSTRIDE 288

// =================== helpers ===================
__device__ __forceinline__ uint32_t smem_u32(const void* p) {
    uint32_t a;
    asm("{ .reg .u64 t; cvta.to.shared.u64 t, %1; cvt.u32.u64 %0, t; }" : "=r"(a) : "l"(p));
    return a;
}
__device__ __forceinline__ void ldsm_x4(uint32_t* r, uint32_t a) {
    asm volatile("ldmatrix.sync.aligned.m8n8.x4.shared.b16 {%0,%1,%2,%3}, [%4];"
                 : "=r"(r[0]), "=r"(r[1]), "=r"(r[2]), "=r"(r[3]) : "r"(a));
}
__device__ __forceinline__ void ldsm_x4_t(uint32_t* r, uint32_t a) {
    asm volatile("ldmatrix.sync.aligned.m8n8.x4.trans.shared.b16 {%0,%1,%2,%3}, [%4];"
                 : "=r"(r[0]), "=r"(r[1]), "=r"(r[2]), "=r"(r[3]) : "r"(a));
}
__device__ __forceinline__ void mma16816(float* c, const uint32_t* a, const uint32_t* b) {
    asm volatile("mma.sync.aligned.m16n8k16.row.col.f32.f16.f16.f32 "
                 "{%0,%1,%2,%3}, {%4,%5,%6,%7}, {%8,%9}, {%0,%1,%2,%3};"
                 : "+f"(c[0]), "+f"(c[1]), "+f"(c[2]), "+f"(c[3])
                 : "r"(a[0]), "r"(a[1]), "r"(a[2]), "r"(a[3]), "r"(b[0]), "r"(b[1]));
}
__device__ __forceinline__ float ex2f(float x) {
    float r;
    asm("ex2.approx.f32 %0, %1;" : "=f"(r) : "f"(x));
    return r;
}
__device__ __forceinline__ void split_pair(uint32_t& hp, uint32_t& lp, float a, float b) {
    __half2 h = __floats2half2_rn(a, b);
    float2 hf = __half22float2(h);
    __half2 l = __floats2half2_rn(a - hf.x, b - hf.y);
    hp = *reinterpret_cast<uint32_t*>(&h);
    lp = *reinterpret_cast<uint32_t*>(&l);
}
__device__ __forceinline__ uint32_t pack_f16(float a, float b) {
    __half2 h = __floats2half2_rn(a, b);
    return *reinterpret_cast<uint32_t*>(&h);
}

#define CP_ASYNC16(sm, gp) \
    asm volatile("cp.async.cg.shared.global [%0], [%1], 16;" :: "r"(sm), "l"(gp) : "memory")
#define CP_COMMIT() asm volatile("cp.async.commit_group;" ::: "memory")
#define CP_WAIT0()  asm volatile("cp.async.wait_group 0;" ::: "memory")

// gmem fp32 tile (128x64) -> raw fp32 staging via cp.async (512 threads)
__device__ __forceinline__ void stage_tile(const float* __restrict__ g,
                                           uint32_t st_base, int tid) {
    const int row = tid >> 2, q = tid & 3;
    const char* gp = (const char*)(g + (size_t)row * DH) + q * 64;
    const uint32_t sp = st_base + row * STSTRIDE + q * 64;
    #pragma unroll
    for (int u = 0; u < 4; u++) CP_ASYNC16(sp + u * 16, gp + u * 16);
}

// staging fp32 -> split fp16 hi/lo tiles
__device__ __forceinline__ void split_from_staging(const char* sm_ro, char* sm,
                                                   int st_off, int oh, int ol, int tid) {
    const int row = tid & 127, dq = tid >> 7;
    const float4* sp = (const float4*)(sm_ro + st_off + row * STSTRIDE + dq * 64);
    char* hrow = sm + oh + row * TSTRIDE + dq * 32;
    char* lrow = sm + ol + row * TSTRIDE + dq * 32;
    #pragma unroll
    for (int u = 0; u < 4; u++) {
        float4 f = sp[u];
        uint32_t h0, l0, h1, l1;
        split_pair(h0, l0, f.x, f.y);
        split_pair(h1, l1, f.z, f.w);
        *(uint2*)(hrow + 8 * u) = make_uint2(h0, h1);
        *(uint2*)(lrow + 8 * u) = make_uint2(l0, l1);
    }
}

// staging fp32 -> single fp16 plane (K)
__device__ __forceinline__ void convert_from_staging(const char* sm_ro, char* sm,
                                                     int st_off, int oh, int tid) {
    const int row = tid & 127, dq = tid >> 7;
    const float4* sp = (const float4*)(sm_ro + st_off + row * STSTRIDE + dq * 64);
    char* hrow = sm + oh + row * TSTRIDE + dq * 32;
    #pragma unroll
    for (int u = 0; u < 4; u++) {
        float4 f = sp[u];
        *(uint2*)(hrow + 8 * u) = make_uint2(pack_f16(f.x, f.y), pack_f16(f.z, f.w));
    }
}

// Q: direct gmem load with prescale, split to hi/lo
__device__ __forceinline__ void load_q_split(const float* __restrict__ g, char* sm, int tid) {
    const int row = tid >> 2, d0 = (tid & 3) << 4;
    const float4* s4 = (const float4*)(g + (size_t)row * DH + d0);
    char* hrow = sm + SM_QH + row * TSTRIDE + d0 * 2;
    char* lrow = sm + SM_QL + row * TSTRIDE + d0 * 2;
    #pragma unroll
    for (int u = 0; u < 4; u++) {
        float4 f = s4[u];
        f.x *= QK_SCALE; f.y *= QK_SCALE; f.z *= QK_SCALE; f.w *= QK_SCALE;
        uint32_t h0, l0, h1, l1;
        split_pair(h0, l0, f.x, f.y);
        split_pair(h1, l1, f.z, f.w);
        *(uint2*)(hrow + 8 * u) = make_uint2(h0, h1);
        *(uint2*)(lrow + 8 * u) = make_uint2(l0, l1);
    }
}

// =================== mask encoding detection (parallel) ===================
__device__ int g_mask_words;   // 0 = u8 bytes, 1 = 4-byte words

__global__ void detect_mask_kernel(const unsigned int* __restrict__ m) {
    __shared__ int bad;
    if (threadIdx.x == 0) bad = 0;
    __syncthreads();
    int ok = 1;
    for (int i = threadIdx.x; i < 4096; i += 256) {
        unsigned int w = m[i];
        if (w != 0u && w != 1u && w != 0x3F800000u) ok = 0;
    }
    if (!ok) bad = 1;
    __syncthreads();
    if (threadIdx.x == 0) g_mask_words = bad ? 0 : 1;
}

// =================== main kernel ===================
__global__ void __launch_bounds__(NTHREADS, 1)
attn_mma_kernel(const float* __restrict__ Q, const float* __restrict__ K,
                const float* __restrict__ V, const void* __restrict__ Mraw,
                float* __restrict__ O) {
    extern __shared__ char sm[];
    const uint32_t smb = smem_u32(sm);
    const int tid  = threadIdx.x;
    const int w    = tid >> 5;
    const int lane = tid & 31;
    const int wq   = w & 7;             // q block: rows wq*16 .. +15
    const int wk   = w >> 3;            // k half:  keys wk*64 .. +63
    const int g    = lane >> 2;
    const int t4   = lane & 3;

    const int b  = blockIdx.y;
    const int q0 = blockIdx.x * BQ;
    const int mask_words = g_mask_words;

    const float* Qb = Q + ((size_t)b * LQ + q0) * DH;
    const float* Kb = K + (size_t)b * LK * DH;
    const float* Vb = V + (size_t)b * LK * DH;
    const size_t mbase = ((size_t)b * LQ + q0) * (size_t)LK;

    // ldmatrix lane bases
    const uint32_t a_base  = smb + (uint32_t)(wq * 16 + (lane & 15)) * TSTRIDE + (lane >> 4) * 16;
    const uint32_t b4_base = smb + (uint32_t)(wk * 64 + (lane & 7) + ((lane & 16) >> 1)) * TSTRIDE
                           + ((lane >> 3) & 1) * 16;
    const uint32_t v4_base = smb + (uint32_t)(wk * 64 + (lane & 15)) * TSTRIDE + (lane >> 4) * 16;
    const char* m_row = sm + SM_MS + (wq * 16 + g) * MSTRIDE + wk * 64 + 2 * t4;

    // mask loader geometry
    const int mqrow = tid >> 2;
    const int mc0   = (tid & 3) << 5;

    // ---- prologue: start staging tile 0, then Q split ----
    stage_tile(Kb, smb + SM_STK, tid);
    stage_tile(Vb, smb + SM_STV, tid);
    CP_COMMIT();

    load_q_split(Qb, sm, tid);

    float oacc[8][4];
    #pragma unroll
    for (int j = 0; j < 8; j++)
        #pragma unroll
        for (int i = 0; i < 4; i++) oacc[j][i] = 0.0f;
    float den[2] = {0.0f, 0.0f};

    for (int t = 0; t < NTILES; t++) {
        __syncthreads();   // previous tile's compute done

        // ---- issue mask LDGs into registers (latency hidden by split) ----
        const size_t me = mbase + (size_t)mqrow * LK + (size_t)t * BK + mc0;
        uint4 mw4[8];
        uint32_t mu[8];
        if (mask_words) {
            const uint4* src = (const uint4*)((const unsigned int*)Mraw + me);
            #pragma unroll
            for (int i = 0; i < 8; i++) mw4[i] = src[i];
        } else {
            const uint32_t* src = (const uint32_t*)((const unsigned char*)Mraw + me);
            #pragma unroll
            for (int i = 0; i < 8; i++) mu[i] = src[i];
        }

        // ---- staging(t) ready -> convert/split to fp16 tiles ----
        CP_WAIT0();
        __syncthreads();
        convert_from_staging(sm, sm, SM_STK, SM_KH, tid);
        split_from_staging(sm, sm, SM_STV, SM_VH, SM_VL, tid);

        // ---- mask STS (data arrived during split) ----
        {
            char* dst = sm + SM_MS + mqrow * MSTRIDE + mc0;
            if (mask_words) {
                #pragma unroll
                for (int i = 0; i < 8; i++) {
                    uint4 mw = mw4[i];
                    uint32_t p = (mw.x ? 1u : 0u) | (mw.y ? 0x100u : 0u)
                               | (mw.z ? 0x10000u : 0u) | (mw.w ? 0x1000000u : 0u);
                    *(uint32_t*)(dst + 4 * i) = p;
                }
            } else {
                #pragma unroll
                for (int i = 0; i < 8; i++) *(uint32_t*)(dst + 4 * i) = mu[i];
            }
        }
        __syncthreads();   // tiles + mask visible

        // ---- start staging t+1 (hidden under compute) ----
        if (t + 1 < NTILES) {
            stage_tile(Kb + (size_t)((t + 1) * BK) * DH, smb + SM_STK, tid);
            stage_tile(Vb + (size_t)((t + 1) * BK) * DH, smb + SM_STV, tid);
            CP_COMMIT();
        }

        // ---- S = Qh·Kh + Ql·Kh  (16 rows x 64 keys per warp) ----
        float sacc[8][4];
        #pragma unroll
        for (int nt = 0; nt < 8; nt++)
            #pragma unroll
            for (int i = 0; i < 4; i++) sacc[nt][i] = 0.0f;

        #pragma unroll
        for (int kt = 0; kt < 4; kt++) {
            uint32_t ah[4], al[4];
            ldsm_x4(ah, a_base + SM_QH + kt * 32);
            ldsm_x4(al, a_base + SM_QL + kt * 32);
            #pragma unroll
            for (int nt2 = 0; nt2 < 4; nt2++) {
                uint32_t bh4[4];
                ldsm_x4(bh4, b4_base + SM_KH + nt2 * (16 * TSTRIDE) + kt * 32);
                mma16816(sacc[2 * nt2],     ah, bh4);
                mma16816(sacc[2 * nt2 + 1], ah, bh4 + 2);
                mma16816(sacc[2 * nt2],     al, bh4);
                mma16816(sacc[2 * nt2 + 1], al, bh4 + 2);
            }
        }

        // ---- epilogue + PV per 16-key group (P single fp16; V split) ----
        #pragma unroll
        for (int kt2 = 0; kt2 < 4; kt2++) {
            const int n0 = 2 * kt2, n1 = n0 + 1;
            const char* mr1 = m_row + 8 * MSTRIDE;
            uint16_t mA0 = *(const uint16_t*)(m_row + n0 * 8);
            uint16_t mB0 = *(const uint16_t*)(mr1 + n0 * 8);
            uint16_t mA1 = *(const uint16_t*)(m_row + n1 * 8);
            uint16_t mB1 = *(const uint16_t*)(mr1 + n1 * 8);

            float p00 = ex2f((mA0 & 0xFF) ? 0.0f : sacc[n0][0]);
            float p01 = ex2f((mA0 >> 8)   ? 0.0f : sacc[n0][1]);
            float p02 = ex2f((mB0 & 0xFF) ? 0.0f : sacc[n0][2]);
            float p03 = ex2f((mB0 >> 8)   ? 0.0f : sacc[n0][3]);
            float p10 = ex2f((mA1 & 0xFF) ? 0.0f : sacc[n1][0]);
            float p11 = ex2f((mA1 >> 8)   ? 0.0f : sacc[n1][1]);
            float p12 = ex2f((mB1 & 0xFF) ? 0.0f : sacc[n1][2]);
            float p13 = ex2f((mB1 >> 8)   ? 0.0f : sacc[n1][3]);

            den[0] += p00 + p01 + p10 + p11;
            den[1] += p02 + p03 + p12 + p13;

            uint32_t ph[4];
            ph[0] = pack_f16(p00, p01);
            ph[1] = pack_f16(p02, p03);
            ph[2] = pack_f16(p10, p11);
            ph[3] = pack_f16(p12, p13);

            const uint32_t vrow = v4_base + kt2 * (16 * TSTRIDE);
            #pragma unroll
            for (int dh = 0; dh < 2; dh++) {
                uint32_t vfh[8], vfl[8];
                #pragma unroll
                for (int jj = 0; jj < 2; jj++) {
                    ldsm_x4_t(vfh + 4 * jj, vrow + SM_VH + (dh * 2 + jj) * 32);
                    ldsm_x4_t(vfl + 4 * jj, vrow + SM_VL + (dh * 2 + jj) * 32);
                }
                #pragma unroll
                for (int jj = 0; jj < 2; jj++) {
                    const int j = dh * 2 + jj;
                    mma16816(oacc[2 * j],     ph, vfh + 4 * jj);
                    mma16816(oacc[2 * j + 1], ph, vfh + 4 * jj + 2);
                    mma16816(oacc[2 * j],     ph, vfl + 4 * jj);
                    mma16816(oacc[2 * j + 1], ph, vfl + 4 * jj + 2);
                }
            }
        }
    }

    // ---- quad-reduce den, publish partials ----
    #pragma unroll
    for (int h = 0; h < 2; h++) {
        den[h] += __shfl_xor_sync(0xFFFFFFFFu, den[h], 1);
        den[h] += __shfl_xor_sync(0xFFFFFFFFu, den[h], 2);
    }
    float* den_s = (float*)(sm + SM_DEN);
    if (t4 == 0) {
        den_s[wk * 128 + wq * 16 + g]     = den[0];
        den_s[wk * 128 + wq * 16 + g + 8] = den[1];
    }
    __syncthreads();   // all reads of Q/V SMEM done; den partials visible

    // ---- wk=1 warps publish O partials into dead Q-tile SMEM ----
    if (wk == 1) {
        const int r0 = wq * 16 + g;
        char* base0 = sm + SM_OSM + r0 * OSTRIDE + 8 * t4;
        char* base1 = base0 + 8 * OSTRIDE;
        #pragma unroll
        for (int j = 0; j < 8; j++) {
            *(float2*)(base0 + j * 32) = make_float2(oacc[j][0], oacc[j][1]);
            *(float2*)(base1 + j * 32) = make_float2(oacc[j][2], oacc[j][3]);
        }
    }
    __syncthreads();

    // ---- wk=0 warps combine + normalize + write ----
    if (wk == 0) {
        const int r0 = wq * 16 + g;
        const float inv0 = 1.0f / (den_s[r0] + den_s[128 + r0]);
        const float inv1 = 1.0f / (den_s[r0 + 8] + den_s[128 + r0 + 8]);
        const char* base0 = sm + SM_OSM + r0 * OSTRIDE + 8 * t4;
        const char* base1 = base0 + 8 * OSTRIDE;
        float* o0 = O + ((size_t)b * LQ + q0 + r0) * DH + 2 * t4;
        float* o1 = o0 + 8 * DH;
        #pragma unroll
        for (int j = 0; j < 8; j++) {
            float2 q0v = *(const float2*)(base0 + j * 32);
            float2 q1v = *(const float2*)(base1 + j * 32);
            *(float2*)(o0 + 8 * j) = make_float2((oacc[j][0] + q0v.x) * inv0,
                                                 (oacc[j][1] + q0v.y) * inv0);
            *(float2*)(o1 + 8 * j) = make_float2((oacc[j][2] + q1v.x) * inv1,
                                                 (oacc[j][3] + q1v.y) * inv1);
        }
    }
}

extern "C" void kernel_launch(void* const* d_in, const int* in_sizes, int n_in,
                              void* d_out, int out_size) {
    int mask_idx = 0;
    for (int i = 1; i < n_in; i++)
        if (in_sizes[i] > in_sizes[mask_idx]) mask_idx = i;

    const float* qkv[3];
    int nq = 0;
    for (int i = 0; i < n_in && nq < 3; i++)
        if (i != mask_idx) qkv[nq++] = (const float*)d_in[i];

    const float* q = qkv[0];
    const float* k = qkv[1];
    const float* v = qkv[2];
    const void*  m = d_in[mask_idx];
    float* o = (float*)d_out;

    const int B = in_sizes[mask_idx] / (LQ * LK);

    cudaFuncSetAttribute(attn_mma_kernel,
                         cudaFuncAttributeMaxDynamicSharedMemorySize, SM_TOTAL);

    detect_mask_kernel<<<1, 256>>>((const unsigned int*)m);

    dim3 grid(LQ / BQ, B);
    attn_mma_kernel<<<grid, NTHREADS, SM_TOTAL>>>(q, k, v, m, o);
}

// round 16
// speedup vs baseline: 1.3400x; 1.0971x over previous
#include <cuda_runtime.h>
#include <cuda_fp16.h>
#include <stdint.h>

// ScaledDotProductAttention (reference semantics, unstable exp):
//   s = (q·k)/8 ; s[mask]=0 ; e=exp(s) ; attn=e/rowsum(e) ; out=attn·v
// fp16 mma.sync, cp.async-staged K/V, exp2-prescaled Q.
//   S  = Qh·Kh + Ql·Kh      (Q split fp16; K single fp16)
//   O += P·V                (P and V single fp16; rel err ~4e-4 total)
// Mask LDG issued before the split phase (latency hidden), STS after.
// 16 warps (8 q-warps x 2 k-warps).

#define LQ 2048
#define LK 2048
#define DH 64
#define BQ 128
#define BK 128
#define NTILES (LK / BK)
#define NTHREADS 512

#define QK_SCALE 0.18033688011112042f   // 0.125 * log2(e)

#define TSTRIDE 144                    // fp16 tile row stride (bytes)
#define TILE_BYTES (128 * TSTRIDE)     // 18432
#define SM_QH 0
#define SM_QL (SM_QH + TILE_BYTES)
#define SM_KH (SM_QL + TILE_BYTES)
#define SM_VH (SM_KH + TILE_BYTES)
#define MSTRIDE 136
#define SM_MS  (SM_VH + TILE_BYTES)        // 73728 mask 128x136
#define SM_DEN (SM_MS + 128 * MSTRIDE)     // 91136 den partials
#define STSTRIDE 272                       // fp32 staging row stride
#define SM_STK (SM_DEN + 1024)             // 92160
#define SM_STV (SM_STK + 128 * STSTRIDE)   // 126976
#define SM_TOTAL (SM_STV + 128 * STSTRIDE) // 161792
#define SM_OSM SM_QH                       // O partial buffer (dead Q tiles)
#define OSTRIDE 288

// =================== helpers ===================
__device__ __forceinline__ uint32_t smem_u32(const void* p) {
    uint32_t a;
    asm("{ .reg .u64 t; cvta.to.shared.u64 t, %1; cvt.u32.u64 %0, t; }" : "=r"(a) : "l"(p));
    return a;
}
__device__ __forceinline__ void ldsm_x4(uint32_t* r, uint32_t a) {
    asm volatile("ldmatrix.sync.aligned.m8n8.x4.shared.b16 {%0,%1,%2,%3}, [%4];"
                 : "=r"(r[0]), "=r"(r[1]), "=r"(r[2]), "=r"(r[3]) : "r"(a));
}
__device__ __forceinline__ void ldsm_x4_t(uint32_t* r, uint32_t a) {
    asm volatile("ldmatrix.sync.aligned.m8n8.x4.trans.shared.b16 {%0,%1,%2,%3}, [%4];"
                 : "=r"(r[0]), "=r"(r[1]), "=r"(r[2]), "=r"(r[3]) : "r"(a));
}
__device__ __forceinline__ void mma16816(float* c, const uint32_t* a, const uint32_t* b) {
    asm volatile("mma.sync.aligned.m16n8k16.row.col.f32.f16.f16.f32 "
                 "{%0,%1,%2,%3}, {%4,%5,%6,%7}, {%8,%9}, {%0,%1,%2,%3};"
                 : "+f"(c[0]), "+f"(c[1]), "+f"(c[2]), "+f"(c[3])
                 : "r"(a[0]), "r"(a[1]), "r"(a[2]), "r"(a[3]), "r"(b[0]), "r"(b[1]));
}
__device__ __forceinline__ float ex2f(float x) {
    float r;
    asm("ex2.approx.f32 %0, %1;" : "=f"(r) : "f"(x));
    return r;
}
__device__ __forceinline__ void split_pair(uint32_t& hp, uint32_t& lp, float a, float b) {
    __half2 h = __floats2half2_rn(a, b);
    float2 hf = __half22float2(h);
    __half2 l = __floats2half2_rn(a - hf.x, b - hf.y);
    hp = *reinterpret_cast<uint32_t*>(&h);
    lp = *reinterpret_cast<uint32_t*>(&l);
}
__device__ __forceinline__ uint32_t pack_f16(float a, float b) {
    __half2 h = __floats2half2_rn(a, b);
    return *reinterpret_cast<uint32_t*>(&h);
}

#define CP_ASYNC16(sm, gp) \
    asm volatile("cp.async.cg.shared.global [%0], [%1], 16;" :: "r"(sm), "l"(gp) : "memory")
#define CP_COMMIT() asm volatile("cp.async.commit_group;" ::: "memory")
#define CP_WAIT0()  asm volatile("cp.async.wait_group 0;" ::: "memory")

// gmem fp32 tile (128x64) -> raw fp32 staging via cp.async (512 threads)
__device__ __forceinline__ void stage_tile(const float* __restrict__ g,
                                           uint32_t st_base, int tid) {
    const int row = tid >> 2, q = tid & 3;
    const char* gp = (const char*)(g + (size_t)row * DH) + q * 64;
    const uint32_t sp = st_base + row * STSTRIDE + q * 64;
    #pragma unroll
    for (int u = 0; u < 4; u++) CP_ASYNC16(sp + u * 16, gp + u * 16);
}

// staging fp32 -> single fp16 plane
__device__ __forceinline__ void convert_from_staging(const char* sm_ro, char* sm,
                                                     int st_off, int oh, int tid) {
    const int row = tid & 127, dq = tid >> 7;
    const float4* sp = (const float4*)(sm_ro + st_off + row * STSTRIDE + dq * 64);
    char* hrow = sm + oh + row * TSTRIDE + dq * 32;
    #pragma unroll
    for (int u = 0; u < 4; u++) {
        float4 f = sp[u];
        *(uint2*)(hrow + 8 * u) = make_uint2(pack_f16(f.x, f.y), pack_f16(f.z, f.w));
    }
}

// Q: direct gmem load with prescale, split to hi/lo
__device__ __forceinline__ void load_q_split(const float* __restrict__ g, char* sm, int tid) {
    const int row = tid >> 2, d0 = (tid & 3) << 4;
    const float4* s4 = (const float4*)(g + (size_t)row * DH + d0);
    char* hrow = sm + SM_QH + row * TSTRIDE + d0 * 2;
    char* lrow = sm + SM_QL + row * TSTRIDE + d0 * 2;
    #pragma unroll
    for (int u = 0; u < 4; u++) {
        float4 f = s4[u];
        f.x *= QK_SCALE; f.y *= QK_SCALE; f.z *= QK_SCALE; f.w *= QK_SCALE;
        uint32_t h0, l0, h1, l1;
        split_pair(h0, l0, f.x, f.y);
        split_pair(h1, l1, f.z, f.w);
        *(uint2*)(hrow + 8 * u) = make_uint2(h0, h1);
        *(uint2*)(lrow + 8 * u) = make_uint2(l0, l1);
    }
}

// =================== mask encoding detection (parallel) ===================
__device__ int g_mask_words;   // 0 = u8 bytes, 1 = 4-byte words

__global__ void detect_mask_kernel(const unsigned int* __restrict__ m) {
    __shared__ int bad;
    if (threadIdx.x == 0) bad = 0;
    __syncthreads();
    int ok = 1;
    for (int i = threadIdx.x; i < 4096; i += 256) {
        unsigned int w = m[i];
        if (w != 0u && w != 1u && w != 0x3F800000u) ok = 0;
    }
    if (!ok) bad = 1;
    __syncthreads();
    if (threadIdx.x == 0) g_mask_words = bad ? 0 : 1;
}

// =================== main kernel ===================
__global__ void __launch_bounds__(NTHREADS, 1)
attn_mma_kernel(const float* __restrict__ Q, const float* __restrict__ K,
                const float* __restrict__ V, const void* __restrict__ Mraw,
                float* __restrict__ O) {
    extern __shared__ char sm[];
    const uint32_t smb = smem_u32(sm);
    const int tid  = threadIdx.x;
    const int w    = tid >> 5;
    const int lane = tid & 31;
    const int wq   = w & 7;             // q block: rows wq*16 .. +15
    const int wk   = w >> 3;            // k half:  keys wk*64 .. +63
    const int g    = lane >> 2;
    const int t4   = lane & 3;

    const int b  = blockIdx.y;
    const int q0 = blockIdx.x * BQ;
    const int mask_words = g_mask_words;

    const float* Qb = Q + ((size_t)b * LQ + q0) * DH;
    const float* Kb = K + (size_t)b * LK * DH;
    const float* Vb = V + (size_t)b * LK * DH;
    const size_t mbase = ((size_t)b * LQ + q0) * (size_t)LK;

    // ldmatrix lane bases
    const uint32_t a_base  = smb + (uint32_t)(wq * 16 + (lane & 15)) * TSTRIDE + (lane >> 4) * 16;
    const uint32_t b4_base = smb + (uint32_t)(wk * 64 + (lane & 7) + ((lane & 16) >> 1)) * TSTRIDE
                           + ((lane >> 3) & 1) * 16;
    const uint32_t v4_base = smb + (uint32_t)(wk * 64 + (lane & 15)) * TSTRIDE + (lane >> 4) * 16;
    const char* m_row = sm + SM_MS + (wq * 16 + g) * MSTRIDE + wk * 64 + 2 * t4;

    // mask loader geometry
    const int mqrow = tid >> 2;
    const int mc0   = (tid & 3) << 5;

    // ---- prologue: start staging tile 0, then Q split ----
    stage_tile(Kb, smb + SM_STK, tid);
    stage_tile(Vb, smb + SM_STV, tid);
    CP_COMMIT();

    load_q_split(Qb, sm, tid);

    float oacc[8][4];
    #pragma unroll
    for (int j = 0; j < 8; j++)
        #pragma unroll
        for (int i = 0; i < 4; i++) oacc[j][i] = 0.0f;
    float den[2] = {0.0f, 0.0f};

    for (int t = 0; t < NTILES; t++) {
        __syncthreads();   // previous tile's compute done

        // ---- issue mask LDGs into registers (latency hidden by convert) ----
        const size_t me = mbase + (size_t)mqrow * LK + (size_t)t * BK + mc0;
        uint4 mw4[8];
        uint32_t mu[8];
        if (mask_words) {
            const uint4* src = (const uint4*)((const unsigned int*)Mraw + me);
            #pragma unroll
            for (int i = 0; i < 8; i++) mw4[i] = src[i];
        } else {
            const uint32_t* src = (const uint32_t*)((const unsigned char*)Mraw + me);
            #pragma unroll
            for (int i = 0; i < 8; i++) mu[i] = src[i];
        }

        // ---- staging(t) ready -> convert to fp16 planes ----
        CP_WAIT0();
        __syncthreads();
        convert_from_staging(sm, sm, SM_STK, SM_KH, tid);
        convert_from_staging(sm, sm, SM_STV, SM_VH, tid);

        // ---- mask STS (data arrived during convert) ----
        {
            char* dst = sm + SM_MS + mqrow * MSTRIDE + mc0;
            if (mask_words) {
                #pragma unroll
                for (int i = 0; i < 8; i++) {
                    uint4 mw = mw4[i];
                    uint32_t p = (mw.x ? 1u : 0u) | (mw.y ? 0x100u : 0u)
                               | (mw.z ? 0x10000u : 0u) | (mw.w ? 0x1000000u : 0u);
                    *(uint32_t*)(dst + 4 * i) = p;
                }
            } else {
                #pragma unroll
                for (int i = 0; i < 8; i++) *(uint32_t*)(dst + 4 * i) = mu[i];
            }
        }
        __syncthreads();   // planes + mask visible

        // ---- start staging t+1 (hidden under compute) ----
        if (t + 1 < NTILES) {
            stage_tile(Kb + (size_t)((t + 1) * BK) * DH, smb + SM_STK, tid);
            stage_tile(Vb + (size_t)((t + 1) * BK) * DH, smb + SM_STV, tid);
            CP_COMMIT();
        }

        // ---- S = Qh·Kh + Ql·Kh  (16 rows x 64 keys per warp) ----
        float sacc[8][4];
        #pragma unroll
        for (int nt = 0; nt < 8; nt++)
            #pragma unroll
            for (int i = 0; i < 4; i++) sacc[nt][i] = 0.0f;

        #pragma unroll
        for (int kt = 0; kt < 4; kt++) {
            uint32_t ah[4], al[4];
            ldsm_x4(ah, a_base + SM_QH + kt * 32);
            ldsm_x4(al, a_base + SM_QL + kt * 32);
            #pragma unroll
            for (int nt2 = 0; nt2 < 4; nt2++) {
                uint32_t bh4[4];
                ldsm_x4(bh4, b4_base + SM_KH + nt2 * (16 * TSTRIDE) + kt * 32);
                mma16816(sacc[2 * nt2],     ah, bh4);
                mma16816(sacc[2 * nt2 + 1], ah, bh4 + 2);
                mma16816(sacc[2 * nt2],     al, bh4);
                mma16816(sacc[2 * nt2 + 1], al, bh4 + 2);
            }
        }

        // ---- epilogue + PV per 16-key group (P and V single fp16) ----
        #pragma unroll
        for (int kt2 = 0; kt2 < 4; kt2++) {
            const int n0 = 2 * kt2, n1 = n0 + 1;
            const char* mr1 = m_row + 8 * MSTRIDE;
            uint16_t mA0 = *(const uint16_t*)(m_row + n0 * 8);
            uint16_t mB0 = *(const uint16_t*)(mr1 + n0 * 8);
            uint16_t mA1 = *(const uint16_t*)(m_row + n1 * 8);
            uint16_t mB1 = *(const uint16_t*)(mr1 + n1 * 8);

            float p00 = ex2f((mA0 & 0xFF) ? 0.0f : sacc[n0][0]);
            float p01 = ex2f((mA0 >> 8)   ? 0.0f : sacc[n0][1]);
            float p02 = ex2f((mB0 & 0xFF) ? 0.0f : sacc[n0][2]);
            float p03 = ex2f((mB0 >> 8)   ? 0.0f : sacc[n0][3]);
            float p10 = ex2f((mA1 & 0xFF) ? 0.0f : sacc[n1][0]);
            float p11 = ex2f((mA1 >> 8)   ? 0.0f : sacc[n1][1]);
            float p12 = ex2f((mB1 & 0xFF) ? 0.0f : sacc[n1][2]);
            float p13 = ex2f((mB1 >> 8)   ? 0.0f : sacc[n1][3]);

            den[0] += p00 + p01 + p10 + p11;
            den[1] += p02 + p03 + p12 + p13;

            uint32_t ph[4];
            ph[0] = pack_f16(p00, p01);
            ph[1] = pack_f16(p02, p03);
            ph[2] = pack_f16(p10, p11);
            ph[3] = pack_f16(p12, p13);

            const uint32_t vrow = v4_base + kt2 * (16 * TSTRIDE);
            uint32_t vf[16];
            #pragma unroll
            for (int jj = 0; jj < 4; jj++)
                ldsm_x4_t(vf + 4 * jj, vrow + SM_VH + jj * 32);
            #pragma unroll
            for (int jj = 0; jj < 4; jj++) {
                mma16816(oacc[2 * jj],     ph, vf + 4 * jj);
                mma16816(oacc[2 * jj + 1], ph, vf + 4 * jj + 2);
            }
        }
    }

    // ---- quad-reduce den, publish partials ----
    #pragma unroll
    for (int h = 0; h < 2; h++) {
        den[h] += __shfl_xor_sync(0xFFFFFFFFu, den[h], 1);
        den[h] += __shfl_xor_sync(0xFFFFFFFFu, den[h], 2);
    }
    float* den_s = (float*)(sm + SM_DEN);
    if (t4 == 0) {
        den_s[wk * 128 + wq * 16 + g]     = den[0];
        den_s[wk * 128 + wq * 16 + g + 8] = den[1];
    }
    __syncthreads();   // all reads of Q/V SMEM done; den partials visible

    // ---- wk=1 warps publish O partials into dead Q-tile SMEM ----
    if (wk == 1) {
        const int r0 = wq * 16 + g;
        char* base0 = sm + SM_OSM + r0 * OSTRIDE + 8 * t4;
        char* base1 = base0 + 8 * OSTRIDE;
        #pragma unroll
        for (int j = 0; j < 8; j++) {
            *(float2*)(base0 + j * 32) = make_float2(oacc[j][0], oacc[j][1]);
            *(float2*)(base1 + j * 32) = make_float2(oacc[j][2], oacc[j][3]);
        }
    }
    __syncthreads();

    // ---- wk=0 warps combine + normalize + write ----
    if (wk == 0) {
        const int r0 = wq * 16 + g;
        const float inv0 = 1.0f / (den_s[r0] + den_s[128 + r0]);
        const float inv1 = 1.0f / (den_s[r0 + 8] + den_s[128 + r0 + 8]);
        const char* base0 = sm + SM_OSM + r0 * OSTRIDE + 8 * t4;
        const char* base1 = base0 + 8 * OSTRIDE;
        float* o0 = O + ((size_t)b * LQ + q0 + r0) * DH + 2 * t4;
        float* o1 = o0 + 8 * DH;
        #pragma unroll
        for (int j = 0; j < 8; j++) {
            float2 q0v = *(const float2*)(base0 + j * 32);
            float2 q1v = *(const float2*)(base1 + j * 32);
            *(float2*)(o0 + 8 * j) = make_float2((oacc[j][0] + q0v.x) * inv0,
                                                 (oacc[j][1] + q0v.y) * inv0);
            *(float2*)(o1 + 8 * j) = make_float2((oacc[j][2] + q1v.x) * inv1,
                                                 (oacc[j][3] + q1v.y) * inv1);
        }
    }
}

extern "C" void kernel_launch(void* const* d_in, const int* in_sizes, int n_in,
                              void* d_out, int out_size) {
    int mask_idx = 0;
    for (int i = 1; i < n_in; i++)
        if (in_sizes[i] > in_sizes[mask_idx]) mask_idx = i;

    const float* qkv[3];
    int nq = 0;
    for (int i = 0; i < n_in && nq < 3; i++)
        if (i != mask_idx) qkv[nq++] = (const float*)d_in[i];

    const float* q = qkv[0];
    const float* k = qkv[1];
    const float* v = qkv[2];
    const void*  m = d_in[mask_idx];
    float* o = (float*)d_out;

    const int B = in_sizes[mask_idx] / (LQ * LK);

    cudaFuncSetAttribute(attn_mma_kernel,
                         cudaFuncAttributeMaxDynamicSharedMemorySize, SM_TOTAL);

    detect_mask_kernel<<<1, 256>>>((const unsigned int*)m);

    dim3 grid(LQ / BQ, B);
    attn_mma_kernel<<<grid, NTHREADS, SM_TOTAL>>>(q, k, v, m, o);
}